// round 10
// baseline (speedup 1.0000x reference)
#include <cuda_runtime.h>
#include <cuda_fp16.h>

#define N_ROW 8192
#define N_COL 8192
#define RANK  256

#define BM 256
#define BN 256
#define BK 32
#define NKT (RANK / BK)      // 8 K-iterations
#define STG_BYTES 32768      // 16 KB A + 16 KB B per stage
#define SMEM_BYTES (3 * STG_BYTES)

// ---------------- device scratch (no dynamic allocation allowed) -----------
__device__ float g_x2[N_ROW];
__device__ float g_y2[N_COL];
__device__ __half g_Xh[(size_t)N_ROW * RANK];   // fp16 X, row-major [M][K]
__device__ __half g_Yh[(size_t)RANK * N_COL];   // fp16 Y, row-major [K][N]

// ---------------- PTX helpers (all baseline sm_80+ features) ---------------
__device__ __forceinline__ unsigned smem_u32(const void* p) {
    unsigned a;
    asm("{ .reg .u64 t; cvta.to.shared.u64 t, %1; cvt.u32.u64 %0, t; }"
        : "=r"(a) : "l"(p));
    return a;
}

#define CP16(dst, src) \
    asm volatile("cp.async.cg.shared.global [%0], [%1], 16;" :: "r"(dst), "l"(src))
#define CPCOMMIT() asm volatile("cp.async.commit_group;" ::: "memory")
#define CPWAIT1()  asm volatile("cp.async.wait_group 1;" ::: "memory")

__device__ __forceinline__ uint4 ldsm4(unsigned a) {
    uint4 r;
    asm volatile("ldmatrix.sync.aligned.m8n8.x4.shared.b16 {%0,%1,%2,%3}, [%4];"
                 : "=r"(r.x), "=r"(r.y), "=r"(r.z), "=r"(r.w) : "r"(a));
    return r;
}
__device__ __forceinline__ uint4 ldsm4t(unsigned a) {
    uint4 r;
    asm volatile("ldmatrix.sync.aligned.m8n8.x4.trans.shared.b16 {%0,%1,%2,%3}, [%4];"
                 : "=r"(r.x), "=r"(r.y), "=r"(r.z), "=r"(r.w) : "r"(a));
    return r;
}
// fp16 inputs, fp16 accumulate: C is 2 packed f16x2 regs (row-groups 0/1)
__device__ __forceinline__ void mma16816h(uint2& c, uint4 a, unsigned b0, unsigned b1) {
    asm volatile(
        "mma.sync.aligned.m16n8k16.row.col.f16.f16.f16.f16 "
        "{%0,%1}, {%2,%3,%4,%5}, {%6,%7}, {%0,%1};"
        : "+r"(c.x), "+r"(c.y)
        : "r"(a.x), "r"(a.y), "r"(a.z), "r"(a.w), "r"(b0), "r"(b1));
}

// ---------------- converters (fused with exact fp32 norms) -----------------
__global__ void convert_x_kernel(const float* __restrict__ X) {
    const int lane = threadIdx.x & 31;
    const int row  = blockIdx.x * 8 + (threadIdx.x >> 5);
    const float4* p = reinterpret_cast<const float4*>(X + (size_t)row * RANK + lane * 8);
    float4 a = p[0], b = p[1];
    float s = 0.f;
    s = fmaf(a.x, a.x, s); s = fmaf(a.y, a.y, s);
    s = fmaf(a.z, a.z, s); s = fmaf(a.w, a.w, s);
    s = fmaf(b.x, b.x, s); s = fmaf(b.y, b.y, s);
    s = fmaf(b.z, b.z, s); s = fmaf(b.w, b.w, s);

    __half2 h0 = __floats2half2_rn(a.x, a.y);
    __half2 h1 = __floats2half2_rn(a.z, a.w);
    __half2 h2 = __floats2half2_rn(b.x, b.y);
    __half2 h3 = __floats2half2_rn(b.z, b.w);
    uint4 v;
    v.x = *reinterpret_cast<unsigned*>(&h0);
    v.y = *reinterpret_cast<unsigned*>(&h1);
    v.z = *reinterpret_cast<unsigned*>(&h2);
    v.w = *reinterpret_cast<unsigned*>(&h3);
    *reinterpret_cast<uint4*>(g_Xh + (size_t)row * RANK + lane * 8) = v;

#pragma unroll
    for (int o = 16; o > 0; o >>= 1) s += __shfl_xor_sync(0xffffffffu, s, o);
    if (lane == 0) g_x2[row] = s;
}

__global__ void convert_y_kernel(const float* __restrict__ Y) {
    const int j = (blockIdx.x * blockDim.x + threadIdx.x) * 2;
    float s0 = 0.f, s1 = 0.f;
#pragma unroll 8
    for (int k = 0; k < RANK; ++k) {
        float2 v = *reinterpret_cast<const float2*>(Y + (size_t)k * N_COL + j);
        s0 = fmaf(v.x, v.x, s0);
        s1 = fmaf(v.y, v.y, s1);
        __half2 h = __floats2half2_rn(v.x, v.y);
        *reinterpret_cast<__half2*>(g_Yh + (size_t)k * N_COL + j) = h;
    }
    g_y2[j]     = s0;
    g_y2[j + 1] = s1;
}

// ---------------- HMMA GEMM + fused epilogue -------------------------------
// A tile [256 rows][32 fp16] = 64B rows (4 chunks):   phys chunk = c ^ ((row>>1)&3)
// B tile [32 krows][256 fp16] = 512B rows (32 chunks): phys chunk = c ^ (kr&7)
// (invariant under the +128-row A / +16-row B loader offsets)
__global__ __launch_bounds__(512, 1)
void l2_mma_kernel(const float* __restrict__ beta, float* __restrict__ out) {
    extern __shared__ __align__(128) char sm[];

    const int tid  = threadIdx.x;
    const int lane = tid & 31;
    const int wid  = tid >> 5;         // 0..15
    const int brow = blockIdx.y * BM;
    const int bcol = blockIdx.x * BN;
    const int wm   = (wid & 3) * 64;   // 4 warp-rows
    const int wn   = (wid >> 2) * 64;  // 4 warp-cols
    const unsigned smb = smem_u32(sm);

    uint2 acc[4][8];                   // f16x2 accumulators, 64 regs
#pragma unroll
    for (int i = 0; i < 4; ++i)
#pragma unroll
        for (int j = 0; j < 8; ++j) acc[i][j] = make_uint2(0u, 0u);

    // ---- loader assignments (invariant across stages/iters) ----
    const int ar = tid >> 2, ac = tid & 3;          // A: rows ar, ar+128
    const unsigned aDst = ar * 64 + (ac ^ ((ar >> 1) & 3)) * 16;
    const int br = tid >> 5, bc = tid & 31;         // B: k-rows br, br+16
    const unsigned bDst = br * 512 + (bc ^ (br & 7)) * 16;

    const char* aSrc = (const char*)(g_Xh + (size_t)(brow + ar) * RANK + ac * 8);
    const char* bSrc = (const char*)(g_Yh + (size_t)br * N_COL + bcol + bc * 8);

    auto load_stage = [&](int s, int kt) {
        const unsigned base = smb + s * STG_BYTES;
        CP16(base + aDst,        aSrc + kt * 64);                            // rows 0-127
        CP16(base + aDst + 8192, aSrc + (size_t)128 * RANK * 2 + kt * 64);   // rows 128-255
        const unsigned bb = base + 16384 + bDst;
        const char* bs = bSrc + (size_t)(kt * BK) * N_COL * 2;
        CP16(bb,            bs);
        CP16(bb + 16 * 512, bs + (size_t)16 * N_COL * 2);
    };

    load_stage(0, 0);
    CPCOMMIT();
    load_stage(1, 1);
    CPCOMMIT();

    const int lr = lane & 15, lc = lane >> 4;

#pragma unroll 1
    for (int kt = 0; kt < NKT; ++kt) {
        CPWAIT1();                 // stage kt resident (kt+1 may be in flight)
        __syncthreads();           // consumers of kt-1 done; kt visible to all

        // prefetch kt+2 into buffer (kt+2)%3 == (kt-1)%3 (freed by the sync above)
        if (kt + 2 < NKT) load_stage((kt + 2) % 3, kt + 2);
        CPCOMMIT();                // commit every iter -> group accounting fixed

        const unsigned sA = smb + (kt % 3) * STG_BYTES;
        const unsigned sB = sA + 16384;

#pragma unroll
        for (int k16 = 0; k16 < 2; ++k16) {
            uint4 af[4];
#pragma unroll
            for (int mt = 0; mt < 4; ++mt) {
                int row = wm + mt * 16 + lr;
                int pc  = (k16 * 2 + lc) ^ ((row >> 1) & 3);
                af[mt] = ldsm4(sA + row * 64 + pc * 16);
            }
            uint4 bfr[4];
#pragma unroll
            for (int nt = 0; nt < 4; ++nt) {
                int kr = k16 * 16 + lr;
                int c  = (wn >> 3) + nt * 2 + lc;
                int pc = c ^ (kr & 7);
                bfr[nt] = ldsm4t(sB + kr * 512 + pc * 16);
            }
#pragma unroll
            for (int mt = 0; mt < 4; ++mt)
#pragma unroll
                for (int nt = 0; nt < 4; ++nt) {
                    mma16816h(acc[mt][nt * 2],     af[mt], bfr[nt].x, bfr[nt].y);
                    mma16816h(acc[mt][nt * 2 + 1], af[mt], bfr[nt].z, bfr[nt].w);
                }
        }
    }

    // ---- fused epilogue: z = beta - sqrt(max(x2 + y2 - 2*cross, 0)) ----
    const float beta_v = __ldg(beta);
    const int g = lane >> 2, t = lane & 3;

    float y2v[8][2];
#pragma unroll
    for (int nn = 0; nn < 8; ++nn) {
        float2 y = *reinterpret_cast<const float2*>(g_y2 + bcol + wn + nn * 8 + t * 2);
        y2v[nn][0] = y.x;
        y2v[nn][1] = y.y;
    }

#pragma unroll
    for (int mt = 0; mt < 4; ++mt) {
        const int r0 = brow + wm + mt * 16 + g;
        const float x0 = g_x2[r0];
        const float x1 = g_x2[r0 + 8];
        float* o0 = out + (size_t)r0 * N_COL + bcol + wn;
        float* o1 = o0 + (size_t)8 * N_COL;
#pragma unroll
        for (int nn = 0; nn < 8; ++nn) {
            float2 c0 = __half22float2(*reinterpret_cast<__half2*>(&acc[mt][nn].x));
            float2 c1 = __half22float2(*reinterpret_cast<__half2*>(&acc[mt][nn].y));
            float2 z0, z1;
            z0.x = beta_v - sqrtf(fmaxf(fmaf(-2.f, c0.x, x0 + y2v[nn][0]), 0.f));
            z0.y = beta_v - sqrtf(fmaxf(fmaf(-2.f, c0.y, x0 + y2v[nn][1]), 0.f));
            z1.x = beta_v - sqrtf(fmaxf(fmaf(-2.f, c1.x, x1 + y2v[nn][0]), 0.f));
            z1.y = beta_v - sqrtf(fmaxf(fmaf(-2.f, c1.y, x1 + y2v[nn][1]), 0.f));
            *reinterpret_cast<float2*>(o0 + nn * 8 + t * 2) = z0;
            *reinterpret_cast<float2*>(o1 + nn * 8 + t * 2) = z1;
        }
    }
}

// ---------------------------------------------------------------------------
extern "C" void kernel_launch(void* const* d_in, const int* in_sizes, int n_in,
                              void* d_out, int out_size) {
    const float* X    = (const float*)d_in[0];  // [8192, 256]
    const float* Y    = (const float*)d_in[1];  // [256, 8192]
    const float* beta = (const float*)d_in[2];  // [1]
    float* out        = (float*)d_out;          // [8192, 8192]

    // Host-side function attribute (not a stream/alloc op) — capture-safe.
    cudaFuncSetAttribute(l2_mma_kernel,
                         cudaFuncAttributeMaxDynamicSharedMemorySize, SMEM_BYTES);

    convert_x_kernel<<<N_ROW / 8, 256>>>(X);
    convert_y_kernel<<<N_COL / 2 / 256, 256>>>(Y);

    dim3 grid(N_COL / BN, N_ROW / BM);          // (32, 32)
    l2_mma_kernel<<<grid, 512, SMEM_BYTES>>>(beta, out);
}

// round 11
// speedup vs baseline: 1.3579x; 1.3579x over previous
#include <cuda_runtime.h>
#include <cuda_fp16.h>

#define N_ROW 8192
#define N_COL 8192
#define RANK  256

#define BM 128
#define BN 256
#define BK 32
#define NKT (RANK / BK)      // 8 K-iterations
#define STG_BYTES 24576      // 8 KB A + 16 KB B per stage
#define SMEM_BYTES (3 * STG_BYTES + 1024)   // +1 KB y2 tile

// ---------------- device scratch (no dynamic allocation allowed) -----------
__device__ float g_x2[N_ROW];
__device__ float g_y2p[8][N_COL];               // per-K-group partial |y|^2
__device__ __half g_Xh[(size_t)N_ROW * RANK];   // fp16 X, row-major [M][K]
__device__ __half g_Yh[(size_t)RANK * N_COL];   // fp16 Y, row-major [K][N]

// ---------------- PTX helpers (all baseline sm_80+ features) ---------------
__device__ __forceinline__ unsigned smem_u32(const void* p) {
    unsigned a;
    asm("{ .reg .u64 t; cvta.to.shared.u64 t, %1; cvt.u32.u64 %0, t; }"
        : "=r"(a) : "l"(p));
    return a;
}

#define CP16(dst, src) \
    asm volatile("cp.async.cg.shared.global [%0], [%1], 16;" :: "r"(dst), "l"(src))
#define CPCOMMIT() asm volatile("cp.async.commit_group;" ::: "memory")
#define CPWAIT1()  asm volatile("cp.async.wait_group 1;" ::: "memory")

__device__ __forceinline__ uint4 ldsm4(unsigned a) {
    uint4 r;
    asm volatile("ldmatrix.sync.aligned.m8n8.x4.shared.b16 {%0,%1,%2,%3}, [%4];"
                 : "=r"(r.x), "=r"(r.y), "=r"(r.z), "=r"(r.w) : "r"(a));
    return r;
}
__device__ __forceinline__ uint4 ldsm4t(unsigned a) {
    uint4 r;
    asm volatile("ldmatrix.sync.aligned.m8n8.x4.trans.shared.b16 {%0,%1,%2,%3}, [%4];"
                 : "=r"(r.x), "=r"(r.y), "=r"(r.z), "=r"(r.w) : "r"(a));
    return r;
}
// fp16 inputs, fp16 accumulate: C is 2 packed f16x2 regs (row-groups 0/1)
__device__ __forceinline__ void mma16816h(uint2& c, uint4 a, unsigned b0, unsigned b1) {
    asm volatile(
        "mma.sync.aligned.m16n8k16.row.col.f16.f16.f16.f16 "
        "{%0,%1}, {%2,%3,%4,%5}, {%6,%7}, {%0,%1};"
        : "+r"(c.x), "+r"(c.y)
        : "r"(a.x), "r"(a.y), "r"(a.z), "r"(a.w), "r"(b0), "r"(b1));
}

// ---------------- converters (fused with exact fp32 norms) -----------------
__global__ void convert_x_kernel(const float* __restrict__ X) {
    const int lane = threadIdx.x & 31;
    const int row  = blockIdx.x * 8 + (threadIdx.x >> 5);
    const float4* p = reinterpret_cast<const float4*>(X + (size_t)row * RANK + lane * 8);
    float4 a = p[0], b = p[1];
    float s = 0.f;
    s = fmaf(a.x, a.x, s); s = fmaf(a.y, a.y, s);
    s = fmaf(a.z, a.z, s); s = fmaf(a.w, a.w, s);
    s = fmaf(b.x, b.x, s); s = fmaf(b.y, b.y, s);
    s = fmaf(b.z, b.z, s); s = fmaf(b.w, b.w, s);

    __half2 h0 = __floats2half2_rn(a.x, a.y);
    __half2 h1 = __floats2half2_rn(a.z, a.w);
    __half2 h2 = __floats2half2_rn(b.x, b.y);
    __half2 h3 = __floats2half2_rn(b.z, b.w);
    uint4 v;
    v.x = *reinterpret_cast<unsigned*>(&h0);
    v.y = *reinterpret_cast<unsigned*>(&h1);
    v.z = *reinterpret_cast<unsigned*>(&h2);
    v.w = *reinterpret_cast<unsigned*>(&h3);
    *reinterpret_cast<uint4*>(g_Xh + (size_t)row * RANK + lane * 8) = v;

#pragma unroll
    for (int o = 16; o > 0; o >>= 1) s += __shfl_xor_sync(0xffffffffu, s, o);
    if (lane == 0) g_x2[row] = s;
}

// Y [256,8192] f32 -> g_Yh fp16 + per-K-group partial squares.
// grid (16, 8): blockIdx.y selects a 32-row K-group -> 128 blocks of work.
__global__ void convert_y_kernel(const float* __restrict__ Y) {
    const int j  = (blockIdx.x * blockDim.x + threadIdx.x) * 2;
    const int k0 = blockIdx.y * 32;
    float s0 = 0.f, s1 = 0.f;
#pragma unroll 8
    for (int kk = 0; kk < 32; ++kk) {
        const int k = k0 + kk;
        float2 v = *reinterpret_cast<const float2*>(Y + (size_t)k * N_COL + j);
        s0 = fmaf(v.x, v.x, s0);
        s1 = fmaf(v.y, v.y, s1);
        __half2 h = __floats2half2_rn(v.x, v.y);
        *reinterpret_cast<__half2*>(g_Yh + (size_t)k * N_COL + j) = h;
    }
    *reinterpret_cast<float2*>(&g_y2p[blockIdx.y][j]) = make_float2(s0, s1);
}

// ---------------- HMMA GEMM + fused epilogue -------------------------------
// A tile [128 rows][32 fp16] = 64B rows (4 chunks):   phys chunk = c ^ ((row>>1)&3)
// B tile [32 krows][256 fp16] = 512B rows (32 chunks): phys chunk = c ^ (kr&7)
__global__ __launch_bounds__(256, 2)
void l2_mma_kernel(const float* __restrict__ beta, float* __restrict__ out) {
    extern __shared__ __align__(128) char sm[];

    const int tid  = threadIdx.x;
    const int lane = tid & 31;
    const int wid  = tid >> 5;
    const int brow = blockIdx.y * BM;
    const int bcol = blockIdx.x * BN;
    const int wm   = (wid & 1) * 64;   // warp M offset (2 warp-rows)
    const int wn   = (wid >> 1) * 64;  // warp N offset (4 warp-cols)
    const unsigned smb = smem_u32(sm);
    float* y2s = reinterpret_cast<float*>(sm + 3 * STG_BYTES);

    // prologue: finalize |y|^2 for this CTA's 256 columns into smem
    {
        float s = 0.f;
#pragma unroll
        for (int p = 0; p < 8; ++p) s += g_y2p[p][bcol + tid];
        y2s[tid] = s;
    }

    uint2 acc[4][8];                   // f16x2 accumulators, 64 regs
#pragma unroll
    for (int i = 0; i < 4; ++i)
#pragma unroll
        for (int j = 0; j < 8; ++j) acc[i][j] = make_uint2(0u, 0u);

    // ---- loader assignments (invariant across stages/iters) ----
    const int ar = tid >> 2, ac = tid & 3;          // A: rows ar, ar+64
    const unsigned aDst = ar * 64 + (ac ^ ((ar >> 1) & 3)) * 16;
    const int br = tid >> 5, bc = tid & 31;         // B: k-rows br, br+8, +16, +24
    const unsigned bDst = br * 512 + (bc ^ (br & 7)) * 16;

    const char* aSrc = (const char*)(g_Xh + (size_t)(brow + ar) * RANK + ac * 8);
    const char* bSrc = (const char*)(g_Yh + (size_t)br * N_COL + bcol + bc * 8);

    auto load_stage = [&](int s, int kt) {
        const unsigned base = smb + s * STG_BYTES;
        CP16(base + aDst,        aSrc + kt * 64);
        CP16(base + aDst + 4096, aSrc + (size_t)64 * RANK * 2 + kt * 64);
        const unsigned bb = base + 8192 + bDst;
        const char* bs = bSrc + (size_t)(kt * BK) * N_COL * 2;
        CP16(bb,             bs);
        CP16(bb + 8  * 512,  bs + (size_t)8  * N_COL * 2);
        CP16(bb + 16 * 512,  bs + (size_t)16 * N_COL * 2);
        CP16(bb + 24 * 512,  bs + (size_t)24 * N_COL * 2);
    };

    load_stage(0, 0);
    CPCOMMIT();
    load_stage(1, 1);
    CPCOMMIT();

    const int lr = lane & 15, lc = lane >> 4;

#pragma unroll
    for (int kt = 0; kt < NKT; ++kt) {
        CPWAIT1();                 // stage kt resident (kt+1 may be in flight)
        __syncthreads();           // consumers of kt-1 done; kt visible to all

        // prefetch kt+2 into buffer (kt+2)%3 == (kt-1)%3 (freed by the sync above)
        if (kt + 2 < NKT) load_stage((kt + 2) % 3, kt + 2);
        CPCOMMIT();                // commit every iter -> group accounting fixed

        const unsigned sA = smb + (kt % 3) * STG_BYTES;
        const unsigned sB = sA + 8192;

#pragma unroll
        for (int k16 = 0; k16 < 2; ++k16) {
            uint4 af[4];
#pragma unroll
            for (int mt = 0; mt < 4; ++mt) {
                int row = wm + mt * 16 + lr;
                int pc  = (k16 * 2 + lc) ^ ((row >> 1) & 3);
                af[mt] = ldsm4(sA + row * 64 + pc * 16);
            }
            uint4 bfr[4];
#pragma unroll
            for (int nt = 0; nt < 4; ++nt) {
                int kr = k16 * 16 + lr;
                int c  = (wn >> 3) + nt * 2 + lc;
                int pc = c ^ (kr & 7);
                bfr[nt] = ldsm4t(sB + kr * 512 + pc * 16);
            }
#pragma unroll
            for (int mt = 0; mt < 4; ++mt)
#pragma unroll
                for (int nt = 0; nt < 4; ++nt) {
                    mma16816h(acc[mt][nt * 2],     af[mt], bfr[nt].x, bfr[nt].y);
                    mma16816h(acc[mt][nt * 2 + 1], af[mt], bfr[nt].z, bfr[nt].w);
                }
        }
    }

    // ---- fused epilogue: z = beta - sqrt(max(x2 + y2 - 2*cross, 0)) ----
    const float beta_v = __ldg(beta);
    const int g = lane >> 2, t = lane & 3;

    float y2v[8][2];
#pragma unroll
    for (int nn = 0; nn < 8; ++nn) {
        y2v[nn][0] = y2s[wn + nn * 8 + t * 2];
        y2v[nn][1] = y2s[wn + nn * 8 + t * 2 + 1];
    }

#pragma unroll
    for (int mt = 0; mt < 4; ++mt) {
        const int r0 = brow + wm + mt * 16 + g;
        const float x0 = g_x2[r0];
        const float x1 = g_x2[r0 + 8];
        float* o0 = out + (size_t)r0 * N_COL + bcol + wn;
        float* o1 = o0 + (size_t)8 * N_COL;
#pragma unroll
        for (int nn = 0; nn < 8; ++nn) {
            float2 c0 = __half22float2(*reinterpret_cast<__half2*>(&acc[mt][nn].x));
            float2 c1 = __half22float2(*reinterpret_cast<__half2*>(&acc[mt][nn].y));
            float2 z0, z1;
            z0.x = beta_v - sqrtf(fmaxf(fmaf(-2.f, c0.x, x0 + y2v[nn][0]), 0.f));
            z0.y = beta_v - sqrtf(fmaxf(fmaf(-2.f, c0.y, x0 + y2v[nn][1]), 0.f));
            z1.x = beta_v - sqrtf(fmaxf(fmaf(-2.f, c1.x, x1 + y2v[nn][0]), 0.f));
            z1.y = beta_v - sqrtf(fmaxf(fmaf(-2.f, c1.y, x1 + y2v[nn][1]), 0.f));
            *reinterpret_cast<float2*>(o0 + nn * 8 + t * 2) = z0;
            *reinterpret_cast<float2*>(o1 + nn * 8 + t * 2) = z1;
        }
    }
}

// ---------------------------------------------------------------------------
extern "C" void kernel_launch(void* const* d_in, const int* in_sizes, int n_in,
                              void* d_out, int out_size) {
    const float* X    = (const float*)d_in[0];  // [8192, 256]
    const float* Y    = (const float*)d_in[1];  // [256, 8192]
    const float* beta = (const float*)d_in[2];  // [1]
    float* out        = (float*)d_out;          // [8192, 8192]

    // Host-side function attribute (not a stream/alloc op) — capture-safe.
    cudaFuncSetAttribute(l2_mma_kernel,
                         cudaFuncAttributeMaxDynamicSharedMemorySize, SMEM_BYTES);

    convert_x_kernel<<<N_ROW / 8, 256>>>(X);
    dim3 ygrid(16, 8);
    convert_y_kernel<<<ygrid, 256>>>(Y);

    dim3 grid(N_COL / BN, N_ROW / BM);          // (32, 64)
    l2_mma_kernel<<<grid, 256, SMEM_BYTES>>>(beta, out);
}

// round 12
// speedup vs baseline: 1.5042x; 1.1077x over previous
#include <cuda_runtime.h>
#include <cuda_fp16.h>

#define N_ROW 8192
#define N_COL 8192
#define RANK  256

#define BM 128
#define BN 256
#define BK 32
#define NKT (RANK / BK)      // 8 K-iterations
#define STG_BYTES 24576      // 8 KB A + 16 KB B per stage
#define SMEM_BYTES (3 * STG_BYTES + 1024)   // +1 KB y2 tile

// ---------------- device scratch (no dynamic allocation allowed) -----------
__device__ float g_x2[N_ROW];
__device__ float g_y2p[8][N_COL];               // per-K-group partial |y|^2
__device__ __half g_Xh[(size_t)N_ROW * RANK];   // fp16 X, row-major [M][K]
__device__ __half g_Yh[(size_t)RANK * N_COL];   // fp16 Y, row-major [K][N]

// ---------------- PTX helpers (all baseline sm_80+ features) ---------------
__device__ __forceinline__ unsigned smem_u32(const void* p) {
    unsigned a;
    asm("{ .reg .u64 t; cvta.to.shared.u64 t, %1; cvt.u32.u64 %0, t; }"
        : "=r"(a) : "l"(p));
    return a;
}
__device__ __forceinline__ float sqrt_approx(float x) {
    float r;
    asm("sqrt.approx.f32 %0, %1;" : "=f"(r) : "f"(x));
    return r;
}

#define CP16(dst, src) \
    asm volatile("cp.async.cg.shared.global [%0], [%1], 16;" :: "r"(dst), "l"(src))
#define CPCOMMIT() asm volatile("cp.async.commit_group;" ::: "memory")
#define CPWAIT1()  asm volatile("cp.async.wait_group 1;" ::: "memory")

__device__ __forceinline__ uint4 ldsm4(unsigned a) {
    uint4 r;
    asm volatile("ldmatrix.sync.aligned.m8n8.x4.shared.b16 {%0,%1,%2,%3}, [%4];"
                 : "=r"(r.x), "=r"(r.y), "=r"(r.z), "=r"(r.w) : "r"(a));
    return r;
}
__device__ __forceinline__ uint4 ldsm4t(unsigned a) {
    uint4 r;
    asm volatile("ldmatrix.sync.aligned.m8n8.x4.trans.shared.b16 {%0,%1,%2,%3}, [%4];"
                 : "=r"(r.x), "=r"(r.y), "=r"(r.z), "=r"(r.w) : "r"(a));
    return r;
}
// fp16 inputs, fp16 accumulate: C is 2 packed f16x2 regs (row-groups 0/1)
__device__ __forceinline__ void mma16816h(uint2& c, uint4 a, unsigned b0, unsigned b1) {
    asm volatile(
        "mma.sync.aligned.m16n8k16.row.col.f16.f16.f16.f16 "
        "{%0,%1}, {%2,%3,%4,%5}, {%6,%7}, {%0,%1};"
        : "+r"(c.x), "+r"(c.y)
        : "r"(a.x), "r"(a.y), "r"(a.z), "r"(a.w), "r"(b0), "r"(b1));
}

// ---------------- merged converter (one launch, X and Y parts) -------------
// blocks [0, 1024)  : X rows  (8 rows per block, warp per row) + g_x2
// blocks [1024,1152): Y K-groups (block b-1024 -> (j-chunk, k-group)) + g_y2p
__global__ void convert_xy_kernel(const float* __restrict__ X,
                                  const float* __restrict__ Y) {
    if (blockIdx.x < 1024) {
        const int lane = threadIdx.x & 31;
        const int row  = blockIdx.x * 8 + (threadIdx.x >> 5);
        const float4* p =
            reinterpret_cast<const float4*>(X + (size_t)row * RANK + lane * 8);
        float4 a = p[0], b = p[1];
        float s = 0.f;
        s = fmaf(a.x, a.x, s); s = fmaf(a.y, a.y, s);
        s = fmaf(a.z, a.z, s); s = fmaf(a.w, a.w, s);
        s = fmaf(b.x, b.x, s); s = fmaf(b.y, b.y, s);
        s = fmaf(b.z, b.z, s); s = fmaf(b.w, b.w, s);

        __half2 h0 = __floats2half2_rn(a.x, a.y);
        __half2 h1 = __floats2half2_rn(a.z, a.w);
        __half2 h2 = __floats2half2_rn(b.x, b.y);
        __half2 h3 = __floats2half2_rn(b.z, b.w);
        uint4 v;
        v.x = *reinterpret_cast<unsigned*>(&h0);
        v.y = *reinterpret_cast<unsigned*>(&h1);
        v.z = *reinterpret_cast<unsigned*>(&h2);
        v.w = *reinterpret_cast<unsigned*>(&h3);
        *reinterpret_cast<uint4*>(g_Xh + (size_t)row * RANK + lane * 8) = v;

#pragma unroll
        for (int o = 16; o > 0; o >>= 1) s += __shfl_xor_sync(0xffffffffu, s, o);
        if (lane == 0) g_x2[row] = s;
    } else {
        const int b  = blockIdx.x - 1024;
        const int bx = b & 15;          // 16 column chunks
        const int kg = b >> 4;          // 8 K-groups
        const int j  = (bx * 256 + threadIdx.x) * 2;
        const int k0 = kg * 32;
        float s0 = 0.f, s1 = 0.f;
#pragma unroll 8
        for (int kk = 0; kk < 32; ++kk) {
            const int k = k0 + kk;
            float2 v = *reinterpret_cast<const float2*>(Y + (size_t)k * N_COL + j);
            s0 = fmaf(v.x, v.x, s0);
            s1 = fmaf(v.y, v.y, s1);
            __half2 h = __floats2half2_rn(v.x, v.y);
            *reinterpret_cast<__half2*>(g_Yh + (size_t)k * N_COL + j) = h;
        }
        *reinterpret_cast<float2*>(&g_y2p[kg][j]) = make_float2(s0, s1);
    }
}

// ---------------- HMMA GEMM + fused epilogue -------------------------------
// A tile [128 rows][32 fp16] = 64B rows (4 chunks):   phys chunk = c ^ ((row>>1)&3)
// B tile [32 krows][256 fp16] = 512B rows (32 chunks): phys chunk = c ^ (kr&7)
__global__ __launch_bounds__(256, 2)
void l2_mma_kernel(const float* __restrict__ beta, float* __restrict__ out) {
    extern __shared__ __align__(128) char sm[];

    const int tid  = threadIdx.x;
    const int lane = tid & 31;
    const int wid  = tid >> 5;
    const int brow = blockIdx.y * BM;
    const int bcol = blockIdx.x * BN;
    const int wm   = (wid & 1) * 64;   // warp M offset (2 warp-rows)
    const int wn   = (wid >> 1) * 64;  // warp N offset (4 warp-cols)
    const unsigned smb = smem_u32(sm);
    float* y2s = reinterpret_cast<float*>(sm + 3 * STG_BYTES);

    // prologue: finalize |y|^2 for this CTA's 256 columns into smem
    {
        float s = 0.f;
#pragma unroll
        for (int p = 0; p < 8; ++p) s += g_y2p[p][bcol + tid];
        y2s[tid] = s;
    }

    uint2 acc[4][8];                   // f16x2 accumulators, 64 regs
#pragma unroll
    for (int i = 0; i < 4; ++i)
#pragma unroll
        for (int j = 0; j < 8; ++j) acc[i][j] = make_uint2(0u, 0u);

    // ---- loader assignments (invariant across stages/iters) ----
    const int ar = tid >> 2, ac = tid & 3;          // A: rows ar, ar+64
    const unsigned aDst = ar * 64 + (ac ^ ((ar >> 1) & 3)) * 16;
    const int br = tid >> 5, bc = tid & 31;         // B: k-rows br, br+8, +16, +24
    const unsigned bDst = br * 512 + (bc ^ (br & 7)) * 16;

    const char* aSrc = (const char*)(g_Xh + (size_t)(brow + ar) * RANK + ac * 8);
    const char* bSrc = (const char*)(g_Yh + (size_t)br * N_COL + bcol + bc * 8);

    auto load_stage = [&](int s, int kt) {
        const unsigned base = smb + s * STG_BYTES;
        CP16(base + aDst,        aSrc + kt * 64);
        CP16(base + aDst + 4096, aSrc + (size_t)64 * RANK * 2 + kt * 64);
        const unsigned bb = base + 8192 + bDst;
        const char* bs = bSrc + (size_t)(kt * BK) * N_COL * 2;
        CP16(bb,             bs);
        CP16(bb + 8  * 512,  bs + (size_t)8  * N_COL * 2);
        CP16(bb + 16 * 512,  bs + (size_t)16 * N_COL * 2);
        CP16(bb + 24 * 512,  bs + (size_t)24 * N_COL * 2);
    };

    load_stage(0, 0);
    CPCOMMIT();
    load_stage(1, 1);
    CPCOMMIT();

    const int lr = lane & 15, lc = lane >> 4;

#pragma unroll
    for (int kt = 0; kt < NKT; ++kt) {
        CPWAIT1();                 // stage kt resident (kt+1 may be in flight)
        __syncthreads();           // consumers of kt-1 done; kt visible to all

        // prefetch kt+2 into buffer (kt+2)%3 == (kt-1)%3 (freed by the sync above)
        if (kt + 2 < NKT) load_stage((kt + 2) % 3, kt + 2);
        CPCOMMIT();                // commit every iter -> group accounting fixed

        const unsigned sA = smb + (kt % 3) * STG_BYTES;
        const unsigned sB = sA + 8192;

#pragma unroll
        for (int k16 = 0; k16 < 2; ++k16) {
            uint4 af[4];
#pragma unroll
            for (int mt = 0; mt < 4; ++mt) {
                int row = wm + mt * 16 + lr;
                int pc  = (k16 * 2 + lc) ^ ((row >> 1) & 3);
                af[mt] = ldsm4(sA + row * 64 + pc * 16);
            }
            uint4 bfr[4];
#pragma unroll
            for (int nt = 0; nt < 4; ++nt) {
                int kr = k16 * 16 + lr;
                int c  = (wn >> 3) + nt * 2 + lc;
                int pc = c ^ (kr & 7);
                bfr[nt] = ldsm4t(sB + kr * 512 + pc * 16);
            }
#pragma unroll
            for (int mt = 0; mt < 4; ++mt)
#pragma unroll
                for (int nt = 0; nt < 4; ++nt) {
                    mma16816h(acc[mt][nt * 2],     af[mt], bfr[nt].x, bfr[nt].y);
                    mma16816h(acc[mt][nt * 2 + 1], af[mt], bfr[nt].z, bfr[nt].w);
                }
        }
    }

    // ---- fused epilogue: z = beta - sqrt(max(x2 + y2 - 2*cross, 0)) ----
    const float beta_v = __ldg(beta);
    const int g = lane >> 2, t = lane & 3;

    float y2v[8][2];
#pragma unroll
    for (int nn = 0; nn < 8; ++nn) {
        y2v[nn][0] = y2s[wn + nn * 8 + t * 2];
        y2v[nn][1] = y2s[wn + nn * 8 + t * 2 + 1];
    }

#pragma unroll
    for (int mt = 0; mt < 4; ++mt) {
        const int r0 = brow + wm + mt * 16 + g;
        const float x0 = g_x2[r0];
        const float x1 = g_x2[r0 + 8];
        float* o0 = out + (size_t)r0 * N_COL + bcol + wn;
        float* o1 = o0 + (size_t)8 * N_COL;
#pragma unroll
        for (int nn = 0; nn < 8; ++nn) {
            float2 c0 = __half22float2(*reinterpret_cast<__half2*>(&acc[mt][nn].x));
            float2 c1 = __half22float2(*reinterpret_cast<__half2*>(&acc[mt][nn].y));
            float2 z0, z1;
            z0.x = beta_v - sqrt_approx(fmaxf(fmaf(-2.f, c0.x, x0 + y2v[nn][0]), 0.f));
            z0.y = beta_v - sqrt_approx(fmaxf(fmaf(-2.f, c0.y, x0 + y2v[nn][1]), 0.f));
            z1.x = beta_v - sqrt_approx(fmaxf(fmaf(-2.f, c1.x, x1 + y2v[nn][0]), 0.f));
            z1.y = beta_v - sqrt_approx(fmaxf(fmaf(-2.f, c1.y, x1 + y2v[nn][1]), 0.f));
            *reinterpret_cast<float2*>(o0 + nn * 8 + t * 2) = z0;
            *reinterpret_cast<float2*>(o1 + nn * 8 + t * 2) = z1;
        }
    }
}

// ---------------------------------------------------------------------------
extern "C" void kernel_launch(void* const* d_in, const int* in_sizes, int n_in,
                              void* d_out, int out_size) {
    const float* X    = (const float*)d_in[0];  // [8192, 256]
    const float* Y    = (const float*)d_in[1];  // [256, 8192]
    const float* beta = (const float*)d_in[2];  // [1]
    float* out        = (float*)d_out;          // [8192, 8192]

    // Host-side function attribute (not a stream/alloc op) — capture-safe.
    cudaFuncSetAttribute(l2_mma_kernel,
                         cudaFuncAttributeMaxDynamicSharedMemorySize, SMEM_BYTES);

    convert_xy_kernel<<<1152, 256>>>(X, Y);

    dim3 grid(N_COL / BN, N_ROW / BM);          // (32, 64)
    l2_mma_kernel<<<grid, 256, SMEM_BYTES>>>(beta, out);
}

// round 13
// speedup vs baseline: 1.5574x; 1.0354x over previous
#include <cuda_runtime.h>
#include <cuda_fp16.h>

#define N_ROW 8192
#define N_COL 8192
#define RANK  256

#define BM 128
#define BN 256
#define BK 32
#define NKT (RANK / BK)      // 8 K-iterations
#define STG_BYTES 24576      // 8 KB A + 16 KB B per stage
#define SMEM_BYTES (3 * STG_BYTES + 1024)   // +1 KB y2 tile

// ---------------- device scratch (no dynamic allocation allowed) -----------
__device__ float g_x2[N_ROW];
__device__ float g_y2p[8][N_COL];               // per-K-group partial |y|^2
__device__ __half g_Xh[(size_t)N_ROW * RANK];   // fp16 X, row-major [M][K]
__device__ __half g_Yh[(size_t)RANK * N_COL];   // fp16 Y, row-major [K][N]

// ---------------- PTX helpers (all baseline sm_80+ features) ---------------
__device__ __forceinline__ unsigned smem_u32(const void* p) {
    unsigned a;
    asm("{ .reg .u64 t; cvta.to.shared.u64 t, %1; cvt.u32.u64 %0, t; }"
        : "=r"(a) : "l"(p));
    return a;
}
__device__ __forceinline__ float sqrt_approx(float x) {
    float r;
    asm("sqrt.approx.f32 %0, %1;" : "=f"(r) : "f"(x));
    return r;
}
// streaming store (output is write-once, never re-read)
__device__ __forceinline__ void stg_cs_f2(float* p, float2 v) {
    asm volatile("st.global.cs.v2.f32 [%0], {%1, %2};"
                 :: "l"(p), "f"(v.x), "f"(v.y) : "memory");
}

#define CP16(dst, src) \
    asm volatile("cp.async.cg.shared.global [%0], [%1], 16;" :: "r"(dst), "l"(src))
#define CPCOMMIT() asm volatile("cp.async.commit_group;" ::: "memory")
#define CPWAIT1()  asm volatile("cp.async.wait_group 1;" ::: "memory")

__device__ __forceinline__ uint4 ldsm4(unsigned a) {
    uint4 r;
    asm volatile("ldmatrix.sync.aligned.m8n8.x4.shared.b16 {%0,%1,%2,%3}, [%4];"
                 : "=r"(r.x), "=r"(r.y), "=r"(r.z), "=r"(r.w) : "r"(a));
    return r;
}
__device__ __forceinline__ uint4 ldsm4t(unsigned a) {
    uint4 r;
    asm volatile("ldmatrix.sync.aligned.m8n8.x4.trans.shared.b16 {%0,%1,%2,%3}, [%4];"
                 : "=r"(r.x), "=r"(r.y), "=r"(r.z), "=r"(r.w) : "r"(a));
    return r;
}
// fp16 inputs, fp16 accumulate: C is 2 packed f16x2 regs (row-groups 0/1)
__device__ __forceinline__ void mma16816h(uint2& c, uint4 a, unsigned b0, unsigned b1) {
    asm volatile(
        "mma.sync.aligned.m16n8k16.row.col.f16.f16.f16.f16 "
        "{%0,%1}, {%2,%3,%4,%5}, {%6,%7}, {%0,%1};"
        : "+r"(c.x), "+r"(c.y)
        : "r"(a.x), "r"(a.y), "r"(a.z), "r"(a.w), "r"(b0), "r"(b1));
}

// ---------------- merged converter (one launch, X and Y parts) -------------
// blocks [0, 512)  : X rows — 2 rows per warp, 4 independent LDG.128 per lane
// blocks [512, 640): Y K-groups (block b-512 -> (j-chunk, k-group)) + g_y2p
__global__ void convert_xy_kernel(const float* __restrict__ X,
                                  const float* __restrict__ Y) {
    if (blockIdx.x < 512) {
        const int lane = threadIdx.x & 31;
        const int r0   = blockIdx.x * 16 + (threadIdx.x >> 5) * 2;  // warp: rows r0, r0+1
        const float4* p0 =
            reinterpret_cast<const float4*>(X + (size_t)r0 * RANK + lane * 8);
        const float4* p1 =
            reinterpret_cast<const float4*>(X + (size_t)(r0 + 1) * RANK + lane * 8);
        // 4 independent loads up front (MLP 4)
        float4 a0 = p0[0], b0 = p0[1];
        float4 a1 = p1[0], b1 = p1[1];

        float s0 = 0.f, s1 = 0.f;
        s0 = fmaf(a0.x, a0.x, s0); s0 = fmaf(a0.y, a0.y, s0);
        s0 = fmaf(a0.z, a0.z, s0); s0 = fmaf(a0.w, a0.w, s0);
        s0 = fmaf(b0.x, b0.x, s0); s0 = fmaf(b0.y, b0.y, s0);
        s0 = fmaf(b0.z, b0.z, s0); s0 = fmaf(b0.w, b0.w, s0);
        s1 = fmaf(a1.x, a1.x, s1); s1 = fmaf(a1.y, a1.y, s1);
        s1 = fmaf(a1.z, a1.z, s1); s1 = fmaf(a1.w, a1.w, s1);
        s1 = fmaf(b1.x, b1.x, s1); s1 = fmaf(b1.y, b1.y, s1);
        s1 = fmaf(b1.z, b1.z, s1); s1 = fmaf(b1.w, b1.w, s1);

        __half2 h0 = __floats2half2_rn(a0.x, a0.y);
        __half2 h1 = __floats2half2_rn(a0.z, a0.w);
        __half2 h2 = __floats2half2_rn(b0.x, b0.y);
        __half2 h3 = __floats2half2_rn(b0.z, b0.w);
        uint4 v0;
        v0.x = *reinterpret_cast<unsigned*>(&h0);
        v0.y = *reinterpret_cast<unsigned*>(&h1);
        v0.z = *reinterpret_cast<unsigned*>(&h2);
        v0.w = *reinterpret_cast<unsigned*>(&h3);
        *reinterpret_cast<uint4*>(g_Xh + (size_t)r0 * RANK + lane * 8) = v0;

        h0 = __floats2half2_rn(a1.x, a1.y);
        h1 = __floats2half2_rn(a1.z, a1.w);
        h2 = __floats2half2_rn(b1.x, b1.y);
        h3 = __floats2half2_rn(b1.z, b1.w);
        uint4 v1;
        v1.x = *reinterpret_cast<unsigned*>(&h0);
        v1.y = *reinterpret_cast<unsigned*>(&h1);
        v1.z = *reinterpret_cast<unsigned*>(&h2);
        v1.w = *reinterpret_cast<unsigned*>(&h3);
        *reinterpret_cast<uint4*>(g_Xh + (size_t)(r0 + 1) * RANK + lane * 8) = v1;

        // two independent butterfly chains share the same latency tail
#pragma unroll
        for (int o = 16; o > 0; o >>= 1) {
            s0 += __shfl_xor_sync(0xffffffffu, s0, o);
            s1 += __shfl_xor_sync(0xffffffffu, s1, o);
        }
        if (lane == 0) {
            g_x2[r0]     = s0;
            g_x2[r0 + 1] = s1;
        }
    } else {
        const int b  = blockIdx.x - 512;
        const int bx = b & 15;          // 16 column chunks
        const int kg = b >> 4;          // 8 K-groups
        const int j  = (bx * 256 + threadIdx.x) * 2;
        const int k0 = kg * 32;
        float s0 = 0.f, s1 = 0.f;
#pragma unroll 8
        for (int kk = 0; kk < 32; ++kk) {
            const int k = k0 + kk;
            float2 v = *reinterpret_cast<const float2*>(Y + (size_t)k * N_COL + j);
            s0 = fmaf(v.x, v.x, s0);
            s1 = fmaf(v.y, v.y, s1);
            __half2 h = __floats2half2_rn(v.x, v.y);
            *reinterpret_cast<__half2*>(g_Yh + (size_t)k * N_COL + j) = h;
        }
        *reinterpret_cast<float2*>(&g_y2p[kg][j]) = make_float2(s0, s1);
    }
}

// ---------------- HMMA GEMM + fused epilogue -------------------------------
// A tile [128 rows][32 fp16] = 64B rows (4 chunks):   phys chunk = c ^ ((row>>1)&3)
// B tile [32 krows][256 fp16] = 512B rows (32 chunks): phys chunk = c ^ (kr&7)
__global__ __launch_bounds__(256, 2)
void l2_mma_kernel(const float* __restrict__ beta, float* __restrict__ out) {
    extern __shared__ __align__(128) char sm[];

    const int tid  = threadIdx.x;
    const int lane = tid & 31;
    const int wid  = tid >> 5;
    const int brow = blockIdx.y * BM;
    const int bcol = blockIdx.x * BN;
    const int wm   = (wid & 1) * 64;   // warp M offset (2 warp-rows)
    const int wn   = (wid >> 1) * 64;  // warp N offset (4 warp-cols)
    const unsigned smb = smem_u32(sm);
    float* y2s = reinterpret_cast<float*>(sm + 3 * STG_BYTES);

    // prologue: finalize |y|^2 for this CTA's 256 columns into smem
    {
        float s = 0.f;
#pragma unroll
        for (int p = 0; p < 8; ++p) s += g_y2p[p][bcol + tid];
        y2s[tid] = s;
    }

    uint2 acc[4][8];                   // f16x2 accumulators, 64 regs
#pragma unroll
    for (int i = 0; i < 4; ++i)
#pragma unroll
        for (int j = 0; j < 8; ++j) acc[i][j] = make_uint2(0u, 0u);

    // ---- loader assignments (invariant across stages/iters) ----
    const int ar = tid >> 2, ac = tid & 3;          // A: rows ar, ar+64
    const unsigned aDst = ar * 64 + (ac ^ ((ar >> 1) & 3)) * 16;
    const int br = tid >> 5, bc = tid & 31;         // B: k-rows br, br+8, +16, +24
    const unsigned bDst = br * 512 + (bc ^ (br & 7)) * 16;

    const char* aSrc = (const char*)(g_Xh + (size_t)(brow + ar) * RANK + ac * 8);
    const char* bSrc = (const char*)(g_Yh + (size_t)br * N_COL + bcol + bc * 8);

    auto load_stage = [&](int s, int kt) {
        const unsigned base = smb + s * STG_BYTES;
        CP16(base + aDst,        aSrc + kt * 64);
        CP16(base + aDst + 4096, aSrc + (size_t)64 * RANK * 2 + kt * 64);
        const unsigned bb = base + 8192 + bDst;
        const char* bs = bSrc + (size_t)(kt * BK) * N_COL * 2;
        CP16(bb,             bs);
        CP16(bb + 8  * 512,  bs + (size_t)8  * N_COL * 2);
        CP16(bb + 16 * 512,  bs + (size_t)16 * N_COL * 2);
        CP16(bb + 24 * 512,  bs + (size_t)24 * N_COL * 2);
    };

    load_stage(0, 0);
    CPCOMMIT();
    load_stage(1, 1);
    CPCOMMIT();

    const int lr = lane & 15, lc = lane >> 4;

#pragma unroll
    for (int kt = 0; kt < NKT; ++kt) {
        CPWAIT1();                 // stage kt resident (kt+1 may be in flight)
        __syncthreads();           // consumers of kt-1 done; kt visible to all

        // prefetch kt+2 into buffer (kt+2)%3 == (kt-1)%3 (freed by the sync above)
        if (kt + 2 < NKT) load_stage((kt + 2) % 3, kt + 2);
        CPCOMMIT();                // commit every iter -> group accounting fixed

        const unsigned sA = smb + (kt % 3) * STG_BYTES;
        const unsigned sB = sA + 8192;

#pragma unroll
        for (int k16 = 0; k16 < 2; ++k16) {
            uint4 af[4];
#pragma unroll
            for (int mt = 0; mt < 4; ++mt) {
                int row = wm + mt * 16 + lr;
                int pc  = (k16 * 2 + lc) ^ ((row >> 1) & 3);
                af[mt] = ldsm4(sA + row * 64 + pc * 16);
            }
            uint4 bfr[4];
#pragma unroll
            for (int nt = 0; nt < 4; ++nt) {
                int kr = k16 * 16 + lr;
                int c  = (wn >> 3) + nt * 2 + lc;
                int pc = c ^ (kr & 7);
                bfr[nt] = ldsm4t(sB + kr * 512 + pc * 16);
            }
#pragma unroll
            for (int mt = 0; mt < 4; ++mt)
#pragma unroll
                for (int nt = 0; nt < 4; ++nt) {
                    mma16816h(acc[mt][nt * 2],     af[mt], bfr[nt].x, bfr[nt].y);
                    mma16816h(acc[mt][nt * 2 + 1], af[mt], bfr[nt].z, bfr[nt].w);
                }
        }
    }

    // ---- fused epilogue: z = beta - sqrt(max(x2 + y2 - 2*cross, 0)) ----
    const float beta_v = __ldg(beta);
    const int g = lane >> 2, t = lane & 3;

    float y2v[8][2];
#pragma unroll
    for (int nn = 0; nn < 8; ++nn) {
        y2v[nn][0] = y2s[wn + nn * 8 + t * 2];
        y2v[nn][1] = y2s[wn + nn * 8 + t * 2 + 1];
    }

#pragma unroll
    for (int mt = 0; mt < 4; ++mt) {
        const int r0 = brow + wm + mt * 16 + g;
        const float x0 = g_x2[r0];
        const float x1 = g_x2[r0 + 8];
        float* o0 = out + (size_t)r0 * N_COL + bcol + wn;
        float* o1 = o0 + (size_t)8 * N_COL;
#pragma unroll
        for (int nn = 0; nn < 8; ++nn) {
            float2 c0 = __half22float2(*reinterpret_cast<__half2*>(&acc[mt][nn].x));
            float2 c1 = __half22float2(*reinterpret_cast<__half2*>(&acc[mt][nn].y));
            float2 z0, z1;
            z0.x = beta_v - sqrt_approx(fmaxf(fmaf(-2.f, c0.x, x0 + y2v[nn][0]), 0.f));
            z0.y = beta_v - sqrt_approx(fmaxf(fmaf(-2.f, c0.y, x0 + y2v[nn][1]), 0.f));
            z1.x = beta_v - sqrt_approx(fmaxf(fmaf(-2.f, c1.x, x1 + y2v[nn][0]), 0.f));
            z1.y = beta_v - sqrt_approx(fmaxf(fmaf(-2.f, c1.y, x1 + y2v[nn][1]), 0.f));
            stg_cs_f2(o0 + nn * 8 + t * 2, z0);
            stg_cs_f2(o1 + nn * 8 + t * 2, z1);
        }
    }
}

// ---------------------------------------------------------------------------
extern "C" void kernel_launch(void* const* d_in, const int* in_sizes, int n_in,
                              void* d_out, int out_size) {
    const float* X    = (const float*)d_in[0];  // [8192, 256]
    const float* Y    = (const float*)d_in[1];  // [256, 8192]
    const float* beta = (const float*)d_in[2];  // [1]
    float* out        = (float*)d_out;          // [8192, 8192]

    // Host-side function attribute (not a stream/alloc op) — capture-safe.
    cudaFuncSetAttribute(l2_mma_kernel,
                         cudaFuncAttributeMaxDynamicSharedMemorySize, SMEM_BYTES);

    convert_xy_kernel<<<640, 256>>>(X, Y);

    dim3 grid(N_COL / BN, N_ROW / BM);          // (32, 64)
    l2_mma_kernel<<<grid, 256, SMEM_BYTES>>>(beta, out);
}